// round 16
// baseline (speedup 1.0000x reference)
#include <cuda_runtime.h>
#include <math.h>

#define SEQ   1024
#define VOCAB 8000
#define EMB   512
#define HID   1024
#define G3    (3*HID)        // 3072
#define NCTA  128            // persistent CTAs (<= 148 SMs, one wave)
#define JC    (HID/NCTA)     // 8 hidden units per CTA
#define TPB   256            // 8 warps -> one j per warp

// ---------------- device scratch (no allocations allowed) ----------------
__device__ float    g_gi_enc[SEQ*G3];   // precomputed x@Wih^T + bih (encoder)
__device__ float    g_gi_dec[SEQ*G3];   // precomputed (decoder, teacher forcing)
__device__ float    g_h[2][HID];        // double-buffered hidden state
__device__ int      g_dec_idx[SEQ];     // decoder input token ids
__device__ int      g_nsteps;           // first_eos+1 (or SEQ)
__device__ unsigned g_arrive = 0;       // grid barrier
__device__ unsigned g_gen    = 0;

// ---------------- grid barrier (release/acquire, sense via generation) ---
__device__ __forceinline__ unsigned atom_add_release_gpu(unsigned* p, unsigned v){
    unsigned old;
    asm volatile("atom.add.release.gpu.u32 %0, [%1], %2;"
                 : "=r"(old) : "l"(p), "r"(v) : "memory");
    return old;
}
__device__ __forceinline__ unsigned ld_acquire_gpu(const unsigned* p){
    unsigned v;
    asm volatile("ld.acquire.gpu.u32 %0, [%1];" : "=r"(v) : "l"(p) : "memory");
    return v;
}
__device__ __forceinline__ void grid_barrier(){
    __syncthreads();
    if (threadIdx.x == 0){
        unsigned gen = ld_acquire_gpu(&g_gen);
        unsigned a = atom_add_release_gpu(&g_arrive, 1u);
        if (a == (unsigned)(NCTA-1)){
            *(volatile unsigned*)&g_arrive = 0u;     // reset before release
            atom_add_release_gpu(&g_gen, 1u);        // release next generation
        } else {
            while (ld_acquire_gpu(&g_gen) == gen) { }
        }
    }
    __syncthreads();
}

// ---------------- prep: decoder inputs + eos cutoff ----------------------
__global__ void prep_kernel(const int* __restrict__ target,
                            const int* __restrict__ sos_p,
                            const int* __restrict__ eos_p){
    int t = threadIdx.x;                     // 1024 threads
    __shared__ int mn;
    if (t == 0) mn = SEQ;
    __syncthreads();
    int eos = *eos_p;
    g_dec_idx[t] = (t == 0) ? *sos_p : target[t-1];
    if (target[t] == eos) atomicMin(&mn, t);
    __syncthreads();
    if (t == 0) g_nsteps = (mn + 1 < SEQ) ? (mn + 1) : SEQ;
}

// ---------------- SGEMM: C[M,N] = gather(A)[M,K] * B[N,K]^T + bias -------
// BM=128, BN=64, BK=16, 256 threads, 8x4 micro-tile. All dims divide tiles.
__global__ void __launch_bounds__(256) sgemm_atbt(
    const float* __restrict__ Abase,  // [*,K] table (gather) or [M,K]
    const int*   __restrict__ rows,   // row index per m, or nullptr
    const float* __restrict__ B,      // [N,K]
    const float* __restrict__ bias,   // [N]
    float* __restrict__ C,            // [M,N]
    int M, int N, int K, int use_nvalid)
{
    const int BK = 16;
    __shared__ float As[16][128];
    __shared__ float Bs[16][64];
    int tid = threadIdx.x;
    int m0 = blockIdx.y * 128, n0 = blockIdx.x * 64;
    int tx = tid & 15, ty = tid >> 4;

    // A: 512 float4 per tile -> 2 per thread
    int aIdx0 = tid, aIdx1 = tid + 256;
    int am0 = aIdx0 >> 2, ak0 = (aIdx0 & 3) * 4;
    int am1 = aIdx1 >> 2, ak1 = (aIdx1 & 3) * 4;
    long arow0 = rows ? (long)rows[m0 + am0] : (long)(m0 + am0);
    long arow1 = rows ? (long)rows[m0 + am1] : (long)(m0 + am1);
    const float* Ap0 = Abase + arow0 * K;
    const float* Ap1 = Abase + arow1 * K;
    // B: 256 float4 per tile -> 1 per thread
    int bn_ = tid >> 2, bk_ = (tid & 3) * 4;
    const float* Bp = B + (long)(n0 + bn_) * K;

    float acc[8][4];
    #pragma unroll
    for (int i = 0; i < 8; ++i)
        #pragma unroll
        for (int j = 0; j < 4; ++j) acc[i][j] = 0.f;

    for (int kt = 0; kt < K; kt += BK){
        float4 va0 = *(const float4*)(Ap0 + kt + ak0);
        float4 va1 = *(const float4*)(Ap1 + kt + ak1);
        float4 vb  = *(const float4*)(Bp  + kt + bk_);
        As[ak0+0][am0]=va0.x; As[ak0+1][am0]=va0.y; As[ak0+2][am0]=va0.z; As[ak0+3][am0]=va0.w;
        As[ak1+0][am1]=va1.x; As[ak1+1][am1]=va1.y; As[ak1+2][am1]=va1.z; As[ak1+3][am1]=va1.w;
        Bs[bk_+0][bn_]=vb.x;  Bs[bk_+1][bn_]=vb.y;  Bs[bk_+2][bn_]=vb.z;  Bs[bk_+3][bn_]=vb.w;
        __syncthreads();
        #pragma unroll
        for (int k = 0; k < BK; ++k){
            float4 a0 = *(const float4*)&As[k][ty*8];
            float4 a1 = *(const float4*)&As[k][ty*8+4];
            float4 b0 = *(const float4*)&Bs[k][tx*4];
            float a_[8] = {a0.x,a0.y,a0.z,a0.w,a1.x,a1.y,a1.z,a1.w};
            float b_[4] = {b0.x,b0.y,b0.z,b0.w};
            #pragma unroll
            for (int i = 0; i < 8; ++i)
                #pragma unroll
                for (int j = 0; j < 4; ++j)
                    acc[i][j] = fmaf(a_[i], b_[j], acc[i][j]);
        }
        __syncthreads();
    }
    int nvalid = use_nvalid ? g_nsteps : M;
    #pragma unroll
    for (int i = 0; i < 8; ++i){
        int m = m0 + ty*8 + i;
        int n = n0 + tx*4;
        float4 o;
        if (m < nvalid){
            o.x = acc[i][0] + bias[n+0];
            o.y = acc[i][1] + bias[n+1];
            o.z = acc[i][2] + bias[n+2];
            o.w = acc[i][3] + bias[n+3];
        } else {
            o = make_float4(0.f, 0.f, 0.f, 0.f);
        }
        *(float4*)(C + (long)m * N + n) = o;
    }
}

// ---------------- recurrent persistent kernel ----------------------------
__device__ __forceinline__ float sigmoidf_(float x){ return 1.f / (1.f + expf(-x)); }

// compute the three gate dot-products (r,z,n) for j = j0 + w; result valid on lane 0
__device__ __forceinline__ void tri_dot(const float* __restrict__ sw,
                                        const float* __restrict__ sh,
                                        int w, int lane,
                                        float& ar, float& az, float& an){
    const float4* wr = (const float4*)(sw + (size_t)( 0 + w) * HID);
    const float4* wz = (const float4*)(sw + (size_t)( 8 + w) * HID);
    const float4* wn = (const float4*)(sw + (size_t)(16 + w) * HID);
    const float4* h4 = (const float4*)sh;
    ar = 0.f; az = 0.f; an = 0.f;
    #pragma unroll
    for (int ii = 0; ii < 8; ++ii){
        int i = lane + ii * 32;
        float4 hh = h4[i];
        float4 A = wr[i];
        ar = fmaf(A.x,hh.x, fmaf(A.y,hh.y, fmaf(A.z,hh.z, fmaf(A.w,hh.w, ar))));
        float4 Bq = wz[i];
        az = fmaf(Bq.x,hh.x, fmaf(Bq.y,hh.y, fmaf(Bq.z,hh.z, fmaf(Bq.w,hh.w, az))));
        float4 Cq = wn[i];
        an = fmaf(Cq.x,hh.x, fmaf(Cq.y,hh.y, fmaf(Cq.z,hh.z, fmaf(Cq.w,hh.w, an))));
    }
    #pragma unroll
    for (int o = 16; o; o >>= 1){
        ar += __shfl_down_sync(0xffffffffu, ar, o);
        az += __shfl_down_sync(0xffffffffu, az, o);
        an += __shfl_down_sync(0xffffffffu, an, o);
    }
}

__device__ __forceinline__ void load_w_slice(float* sw, const float* __restrict__ W, int j0){
    // 24 rows x 1024 floats: rows 0..7 = r-gate, 8..15 = z-gate, 16..23 = n-gate
    for (int i = threadIdx.x; i < 24 * (HID/4); i += TPB){
        int r = i >> 8;            // local row
        int c = i & 255;           // float4 col
        int g = r >> 3, ww = r & 7;
        ((float4*)(sw + (size_t)r * HID))[c] =
            ((const float4*)(W + (size_t)(g * HID + j0 + ww) * HID))[c];
    }
}

__global__ void __launch_bounds__(TPB, 1) gru_persist(
    const int*   __restrict__ char_seq,
    const float* __restrict__ enc_state,
    const float* __restrict__ enc_whh, const float* __restrict__ enc_bhh,
    const float* __restrict__ dec_whh, const float* __restrict__ dec_bhh,
    float* __restrict__ states)       // [SEQ, HID] region of d_out
{
    extern __shared__ float sm[];
    float* sw = sm;                  // 24*HID weights slice (96 KB)
    float* sh = sm + 24 * HID;       // HID hidden state copy (4 KB)
    int tid = threadIdx.x;
    int j0  = blockIdx.x * JC;
    int w = tid >> 5, lane = tid & 31;

    load_w_slice(sw, enc_whh, j0);
    if (tid < JC) g_h[0][j0 + tid] = enc_state[j0 + tid];
    grid_barrier();

    int p = 0;

    // ------------------ encoder: 1024 masked GRU steps ------------------
    for (int t = 0; t < SEQ; ++t){
        float4 hv = __ldcg(((const float4*)g_h[p]) + tid);   // bypass L1 (cross-SM)
        ((float4*)sh)[tid] = hv;
        __syncthreads();

        const float* gi = g_gi_enc + (size_t)t * G3;
        int j = j0 + w;
        float gir = gi[j], giz = gi[HID + j], gin = gi[2*HID + j];
        float br = enc_bhh[j], bz = enc_bhh[HID + j], bn = enc_bhh[2*HID + j];
        int ct = char_seq[t];

        float ar, az, an;
        tri_dot(sw, sh, w, lane, ar, az, an);

        if (lane == 0){
            float r = sigmoidf_(gir + ar + br);
            float z = sigmoidf_(giz + az + bz);
            float n = tanhf(gin + r * (an + bn));
            float hp = sh[j];
            float hn = (1.f - z) * n + z * hp;
            if (ct == 0) hn = hp;                 // mask: keep state on pad tokens
            g_h[p ^ 1][j] = hn;
        }
        grid_barrier();
        p ^= 1;
    }

    // ------------------ decoder: n_steps GRU steps -----------------------
    load_w_slice(sw, dec_whh, j0);
    __syncthreads();
    int nsteps = g_nsteps;

    for (int t = 0; t < nsteps; ++t){
        float4 hv = __ldcg(((const float4*)g_h[p]) + tid);
        ((float4*)sh)[tid] = hv;
        __syncthreads();

        const float* gi = g_gi_dec + (size_t)t * G3;
        int j = j0 + w;
        float gir = gi[j], giz = gi[HID + j], gin = gi[2*HID + j];
        float br = dec_bhh[j], bz = dec_bhh[HID + j], bn = dec_bhh[2*HID + j];

        float ar, az, an;
        tri_dot(sw, sh, w, lane, ar, az, an);

        if (lane == 0){
            float r = sigmoidf_(gir + ar + br);
            float z = sigmoidf_(giz + az + bz);
            float n = tanhf(gin + r * (an + bn));
            float hp = sh[j];
            float hn = (1.f - z) * n + z * hp;
            g_h[p ^ 1][j] = hn;
            states[(size_t)t * HID + j] = hn;     // valid[t]==1 for t<nsteps
        }
        grid_barrier();
        p ^= 1;
    }

    // zero-pad states beyond eos cutoff
    for (int t = nsteps; t < SEQ; ++t)
        if (tid < JC) states[(size_t)t * HID + j0 + tid] = 0.f;
}

// ---------------- launch ---------------------------------------------------
extern "C" void kernel_launch(void* const* d_in, const int* in_sizes, int n_in,
                              void* d_out, int out_size)
{
    const int*   char_seq  = (const int*)  d_in[0];
    const int*   target    = (const int*)  d_in[1];
    const float* enc_state = (const float*)d_in[2];
    const float* emb       = (const float*)d_in[3];
    const float* enc_wih   = (const float*)d_in[4];
    const float* enc_whh   = (const float*)d_in[5];
    const float* enc_bih   = (const float*)d_in[6];
    const float* enc_bhh   = (const float*)d_in[7];
    const float* dec_wih   = (const float*)d_in[8];
    const float* dec_whh   = (const float*)d_in[9];
    const float* dec_bih   = (const float*)d_in[10];
    const float* dec_bhh   = (const float*)d_in[11];
    const float* out_w     = (const float*)d_in[12];
    const float* out_b     = (const float*)d_in[13];
    const int*   sos_p     = (const int*)  d_in[14];
    const int*   eos_p     = (const int*)  d_in[15];

    float* out    = (float*)d_out;
    float* scores = out;                          // [SEQ, VOCAB]
    float* states = out + (size_t)SEQ * VOCAB;    // [SEQ, HID]

    void *p_gi_enc = nullptr, *p_gi_dec = nullptr, *p_dec_idx = nullptr;
    cudaGetSymbolAddress(&p_gi_enc, g_gi_enc);
    cudaGetSymbolAddress(&p_gi_dec, g_gi_dec);
    cudaGetSymbolAddress(&p_dec_idx, g_dec_idx);

    // 1) decoder input ids + eos cutoff
    prep_kernel<<<1, SEQ>>>(target, sos_p, eos_p);

    // 2) input-side gates for all steps (parallel GEMMs)
    sgemm_atbt<<<dim3(G3/64, SEQ/128), 256>>>(
        emb, char_seq, enc_wih, enc_bih, (float*)p_gi_enc, SEQ, G3, EMB, 0);
    sgemm_atbt<<<dim3(G3/64, SEQ/128), 256>>>(
        emb, (const int*)p_dec_idx, dec_wih, dec_bih, (float*)p_gi_dec, SEQ, G3, EMB, 0);

    // 3) sequential recurrence: persistent kernel, weights SMEM-resident
    size_t smem = (size_t)(24 * HID + HID) * sizeof(float);   // 100 KB
    cudaFuncSetAttribute(gru_persist, cudaFuncAttributeMaxDynamicSharedMemorySize, (int)smem);
    gru_persist<<<NCTA, TPB, smem>>>(char_seq, enc_state,
                                     enc_whh, enc_bhh, dec_whh, dec_bhh, states);

    // 4) output projection (rows >= n_steps zeroed per valid mask)
    sgemm_atbt<<<dim3(VOCAB/64, SEQ/128), 256>>>(
        states, nullptr, out_w, out_b, scores, SEQ, VOCAB, HID, 1);
}